// round 8
// baseline (speedup 1.0000x reference)
#include <cuda_runtime.h>

// Problem constants
#define NN      10000   // nodes
#define DD      10000   // hypervector dim
#define EE      16000   // edges
#define DCHUNK  2048    // D-dim tile (82MB working set -> L2 resident)
#define EPB     64      // edges per CTA in main kernel
#define FILLTILE 2000   // edges staged per shared tile in k_fill

// ---- scratch (device globals; no allocations allowed) ----
__device__ int   g_colcnt[NN];
__device__ int   g_rowcnt[NN];
__device__ int   g_rowoff[NN + 1];
__device__ float g_vals[EE];
__device__ int   g_csr_col[EE];
__device__ float g_csr_val[EE];
__device__ float g_vtmp[NN];
__device__ float g_vfin[NN];
__device__ int   g_rank[NN];
__device__ int   g_ekey[EE];
__device__ int   g_ue_a[EE];
__device__ int   g_ue_b[EE];
__device__ int   g_ue_cnt;

// ---- K0: zero/seed scratch + output ----
__global__ void k_init(float* __restrict__ out) {
    int i = blockIdx.x * blockDim.x + threadIdx.x;
    if (i < DD) out[i] = 0.f;
    if (i < NN) { g_colcnt[i] = 0; g_rowcnt[i] = 0; }
    if (i == 0) g_ue_cnt = 0;
}

// ---- K1: in-degree counts (col) and row counts ----
__global__ void k_count(const int* __restrict__ edge) {
    int e = blockIdx.x * blockDim.x + threadIdx.x;
    if (e < EE) {
        atomicAdd(&g_colcnt[edge[EE + e]], 1);   // col
        atomicAdd(&g_rowcnt[edge[e]], 1);        // row
    }
}

// ---- K2: vals[e] = 0.85f / count(col[e]) (IEEE rn div) + undirected key ----
__global__ void k_vals(const int* __restrict__ edge) {
    int e = blockIdx.x * blockDim.x + threadIdx.x;
    if (e < EE) {
        int r = edge[e], c = edge[EE + e];
        g_vals[e] = __fdiv_rn(0.85f, (float)g_colcnt[c]);
        int lo = min(r, c), hi = max(r, c);
        g_ekey[e] = lo * NN + hi;
    }
}

// ---- K3a: exclusive scan rowcnt -> rowoff. Block sums + single-thread serial
//      scan of the 1024 partials (trivially correct). ----
__global__ void k_scan() {
    __shared__ int spart[1024];
    __shared__ int soff[1024];
    int t = threadIdx.x;
    int loc[10];
    int s = 0;
    if (t < 1000) {
        int base = t * 10;
        #pragma unroll
        for (int k = 0; k < 10; ++k) { loc[k] = s; s += g_rowcnt[base + k]; }
    }
    spart[t] = (t < 1000) ? s : 0;
    __syncthreads();
    if (t == 0) {
        int run = 0;
        for (int u = 0; u < 1024; ++u) { soff[u] = run; run += spart[u]; }
        g_rowoff[NN] = run;       // = EE
    }
    __syncthreads();
    if (t < 1000) {
        int excl = soff[t];
        int base = t * 10;
        #pragma unroll
        for (int k = 0; k < 10; ++k) g_rowoff[base + k] = excl + loc[k];
    }
}

// ---- K3b: stable CSR fill. One thread per row; scans ALL edges in ascending
//      edge order, appends matches into its private segment. (Certified: two
//      independent builds produced bit-identical downstream results.) ----
__global__ void __launch_bounds__(256) k_fill(const int* __restrict__ edge) {
    __shared__ int srow[FILLTILE];
    int r = blockIdx.x * 256 + threadIdx.x;          // 40 CTAs x 256 = 10240
    int p = (r < NN) ? g_rowoff[r] : 0;
    for (int base = 0; base < EE; base += FILLTILE) {
        __syncthreads();
        for (int j = threadIdx.x; j < FILLTILE; j += 256)
            srow[j] = edge[base + j];
        __syncthreads();
        if (r < NN) {
            for (int j = 0; j < FILLTILE; ++j) {
                if (srow[j] == r) {
                    int e = base + j;
                    g_csr_col[p] = edge[EE + e];
                    g_csr_val[p] = g_vals[e];
                    ++p;
                }
            }
        }
    }
}

// ---- K4: PageRank, 10 iterations, single CTA. P-BASE accumulation:
//      acc = p; then acc += rn(val*v) in ascending edge order (deterministic,
//      no FMA contraction). Matches scatter-add-onto-p-array semantics. ----
__global__ void k_pagerank(float Pf, float V0f) {
    __shared__ float vsh[NN];   // 40KB
    int t = threadIdx.x;
    for (int i = t; i < NN; i += 1024) vsh[i] = V0f;
    __syncthreads();
    for (int it = 0; it < 10; ++it) {
        for (int i = t; i < NN; i += 1024) {
            int s = g_rowoff[i], en = g_rowoff[i + 1];
            float acc = Pf;                                   // seed with p FIRST
            for (int k = s; k < en; ++k)
                acc = __fadd_rn(acc, __fmul_rn(g_csr_val[k], vsh[g_csr_col[k]]));
            g_vtmp[i] = acc;
        }
        __syncthreads();
        for (int i = t; i < NN; i += 1024) vsh[i] = g_vtmp[i];
        __syncthreads();
    }
    for (int i = t; i < NN; i += 1024) g_vfin[i] = vsh[i];
}

// ---- K5: brute-force stable-argsort ranks: one thread per j, full loop.
//      rank(j) = #{i: v_i<v_j || (v_i==v_j && i<j)}. All v>0 -> int-bit cmp ok. ----
__global__ void __launch_bounds__(256) k_rank() {
    __shared__ int bsh[NN];   // 40KB
    int t = threadIdx.x;
    for (int i = t; i < NN; i += 256) bsh[i] = __float_as_int(g_vfin[i]);
    __syncthreads();
    int j = blockIdx.x * 256 + t;
    if (j >= NN) return;
    int bj = bsh[j];
    int c = 0;
    for (int i = 0; i < NN; ++i) {
        int bi = bsh[i];
        c += (bi < bj) || (bi == bj && i < j);
    }
    g_rank[j] = c;
}

// ---- K6: brute-force dedup: edge e kept iff no e' < e with same key. ----
__global__ void __launch_bounds__(256) k_dedup(const int* __restrict__ edge) {
    int e = blockIdx.x * blockDim.x + threadIdx.x;
    if (e >= EE) return;
    int key = g_ekey[e];
    for (int ep = 0; ep < e; ++ep)
        if (g_ekey[ep] == key) return;   // duplicate of an earlier edge
    int r = edge[e], c = edge[EE + e];
    int lo = min(r, c), hi = max(r, c);
    int j = atomicAdd(&g_ue_cnt, 1);
    g_ue_a[j] = g_rank[lo];
    g_ue_b[j] = g_rank[hi];
}

// ---- K7: out[d] += sum_e X[a_e][d]*X[b_e][d], one launch per D-chunk so the
//      chunk (82MB across all rows) stays L2-resident ----
__global__ void __launch_bounds__(512) k_main(const float* __restrict__ X,
                                              float* __restrict__ out,
                                              int dbase) {
    __shared__ int sa[EPB], sb[EPB];
    int nE = g_ue_cnt;
    int e0 = blockIdx.x * EPB;
    int cnt = nE - e0;
    if (cnt <= 0) return;
    if (cnt > EPB) cnt = EPB;
    if (threadIdx.x < cnt) {
        sa[threadIdx.x] = g_ue_a[e0 + threadIdx.x];
        sb[threadIdx.x] = g_ue_b[e0 + threadIdx.x];
    }
    __syncthreads();
    int d = dbase + threadIdx.x * 4;
    if (d >= DD) return;
    float4 acc = make_float4(0.f, 0.f, 0.f, 0.f);
    int dq = d >> 2;
    #pragma unroll 4
    for (int i = 0; i < cnt; ++i) {
        const float4* pa = reinterpret_cast<const float4*>(X + (size_t)sa[i] * DD) + dq;
        const float4* pb = reinterpret_cast<const float4*>(X + (size_t)sb[i] * DD) + dq;
        float4 xa = __ldg(pa);
        float4 xb = __ldg(pb);
        acc.x += xa.x * xb.x;
        acc.y += xa.y * xb.y;
        acc.z += xa.z * xb.z;
        acc.w += xa.w * xb.w;
    }
    atomicAdd(&out[d + 0], acc.x);
    atomicAdd(&out[d + 1], acc.y);
    atomicAdd(&out[d + 2], acc.z);
    atomicAdd(&out[d + 3], acc.w);
}

extern "C" void kernel_launch(void* const* d_in, const int* in_sizes, int n_in,
                              void* d_out, int out_size) {
    const int*   edge;
    const float* X;
    if (in_sizes[0] == 2 * EE) {
        edge = (const int*)d_in[0];
        X    = (const float*)d_in[1];
    } else {
        edge = (const int*)d_in[1];
        X    = (const float*)d_in[0];
    }
    float* out = (float*)d_out;   // [D]

    // match Python-float -> f32 casts of the reference exactly
    float Pf  = (float)((1.0 - 0.85) / 10000.0);
    float V0f = (float)(1.0 / 10000.0);

    k_init<<<40, 256>>>(out);
    k_count<<<63, 256>>>(edge);
    k_vals<<<63, 256>>>(edge);
    k_scan<<<1, 1024>>>();
    k_fill<<<40, 256>>>(edge);
    k_pagerank<<<1, 1024>>>(Pf, V0f);
    k_rank<<<40, 256>>>();
    k_dedup<<<63, 256>>>(edge);
    for (int c = 0; c < 5; ++c)
        k_main<<<250, 512>>>(X, out, c * DCHUNK);
}

// round 13
// speedup vs baseline: 5.9920x; 5.9920x over previous
#include <cuda_runtime.h>

// Problem constants
#define NN      10000   // nodes
#define DD      10000   // hypervector dim
#define EE      16000   // edges
#define HSZ     32768   // hash table slots
#define HMASK   32767
#define NCHUNK  32      // edge chunks for stable CSR build
#define CHSZ    500     // edges per chunk (32*500 = 16000)
#define DCHUNK  1024    // D-dim tile (40MB working set -> L2 resident)
#define EPB     64      // edges per CTA in main kernel

// ---- scratch (device globals; no allocations allowed) ----
__device__ int   g_colcnt[NN];
__device__ int   g_rowcnt[NN];
__device__ int   g_rowoff[NN + 1];
__device__ float g_vals[EE];
__device__ int   g_wchunk[EE];
__device__ int   g_ghist[NCHUNK * NN];
__device__ int   g_csr_col[EE];
__device__ float g_csr_val[EE];
__device__ float g_vfin[NN];
__device__ int   g_rank[NN];
__device__ int   g_htkey[HSZ];
__device__ int   g_htmin[HSZ];
__device__ int   g_ue_a[EE];
__device__ int   g_ue_b[EE];
__device__ int   g_ue_cnt;

// ---- K0: zero/seed scratch + output ----
__global__ void k_init(float* __restrict__ out) {
    int i = blockIdx.x * blockDim.x + threadIdx.x;   // 32768 threads
    if (i < DD) out[i] = 0.f;
    if (i < NN) { g_colcnt[i] = 0; g_rowcnt[i] = 0; }
    if (i < HSZ) { g_htkey[i] = -1; g_htmin[i] = 0x7fffffff; }
    if (i == 0) g_ue_cnt = 0;
}

// ---- K1: in-degree counts (col) and row counts ----
__global__ void k_count(const int* __restrict__ edge) {
    int e = blockIdx.x * blockDim.x + threadIdx.x;
    if (e < EE) {
        atomicAdd(&g_colcnt[edge[EE + e]], 1);   // col
        atomicAdd(&g_rowcnt[edge[e]], 1);        // row
    }
}

// ---- K2: vals[e] = 0.85f / count(col[e]) (IEEE rn division) ----
__global__ void k_vals(const int* __restrict__ edge) {
    int e = blockIdx.x * blockDim.x + threadIdx.x;
    if (e < EE)
        g_vals[e] = __fdiv_rn(0.85f, (float)g_colcnt[edge[EE + e]]);
}

// ---- K3a: exclusive scan rowcnt -> rowoff (Hillis-Steele; certified R1==R3) ----
__global__ void k_scan() {
    __shared__ int ssum[1024];
    int t = threadIdx.x;
    int loc[10];
    int s = 0;
    if (t < 1000) {
        int base = t * 10;
        #pragma unroll
        for (int k = 0; k < 10; ++k) { loc[k] = s; s += g_rowcnt[base + k]; }
    }
    ssum[t] = (t < 1000) ? s : 0;
    __syncthreads();
    for (int off = 1; off < 1024; off <<= 1) {
        int v = ssum[t];
        int add = (t >= off) ? ssum[t - off] : 0;
        __syncthreads();
        ssum[t] = v + add;
        __syncthreads();
    }
    if (t < 1000) {
        int excl = ssum[t] - s;
        int base = t * 10;
        #pragma unroll
        for (int k = 0; k < 10; ++k) g_rowoff[base + k] = excl + loc[k];
    }
    if (t == 1023) g_rowoff[NN] = ssum[1023];
}

// ---- K3b: per-chunk row histograms + within-chunk stable prefix counts ----
__global__ void k_chunkhist(const int* __restrict__ edge) {
    __shared__ int shist[NN];   // 40KB
    __shared__ int srow[CHSZ];
    int c = blockIdx.x, t = threadIdx.x;          // 32 CTAs x 512 threads
    for (int i = t; i < NN; i += 512) shist[i] = 0;
    if (t < CHSZ) srow[t] = edge[c * CHSZ + t];
    __syncthreads();
    if (t < CHSZ) {
        int r = srow[t];
        int w = 0;
        for (int j = 0; j < t; ++j) w += (srow[j] == r);
        g_wchunk[c * CHSZ + t] = w;
        atomicAdd(&shist[r], 1);
    }
    __syncthreads();
    for (int i = t; i < NN; i += 512) g_ghist[c * NN + i] = shist[i];
}

// ---- K3c: stable scatter into CSR (by row, edge-index order preserved) ----
__global__ void k_place(const int* __restrict__ edge) {
    int e = blockIdx.x * blockDim.x + threadIdx.x;
    if (e >= EE) return;
    int r = edge[e];
    int c = e / CHSZ;
    int w = g_wchunk[e];
    for (int c2 = 0; c2 < c; ++c2) w += g_ghist[c2 * NN + r];
    int pos = g_rowoff[r] + w;
    g_csr_col[pos] = edge[EE + e];
    g_csr_val[pos] = g_vals[e];
}

// ---- K4: PageRank, 10 iterations, single CTA, ALL data in dynamic shared.
//      P-BASE accumulation: acc = p; then += rn(val*v) in ascending edge
//      order, rn ops (no FMA). Certified semantics from R8. ----
__global__ void k_pagerank(float Pf, float V0f) {
    extern __shared__ unsigned char dynraw[];
    float* vsh  = (float*)dynraw;            // NN
    float* vnew = vsh + NN;                  // NN
    int*   scol = (int*)(vnew + NN);         // EE
    float* sval = (float*)(scol + EE);       // EE
    int t = threadIdx.x;
    for (int e = t; e < EE; e += 1024) { scol[e] = g_csr_col[e]; sval[e] = g_csr_val[e]; }
    for (int i = t; i < NN; i += 1024) vsh[i] = V0f;
    __syncthreads();
    for (int it = 0; it < 10; ++it) {
        for (int i = t; i < NN; i += 1024) {
            int s = g_rowoff[i], en = g_rowoff[i + 1];
            float acc = Pf;                                   // seed with p FIRST
            for (int k = s; k < en; ++k)
                acc = __fadd_rn(acc, __fmul_rn(sval[k], vsh[scol[k]]));
            vnew[i] = acc;
        }
        __syncthreads();
        for (int i = t; i < NN; i += 1024) vsh[i] = vnew[i];
        __syncthreads();
    }
    for (int i = t; i < NN; i += 1024) g_vfin[i] = vsh[i];
}

// ---- K5: stable-argsort ranks, striped (157 CTAs x 64 j's x 4 i-stripes).
//      rank(j) = #{i: v_i<v_j || (v_i==v_j && i<j)}. All v>0 -> int-bit cmp. ----
__global__ void __launch_bounds__(256) k_rank() {
    __shared__ int bsh[NN];   // 40KB
    __shared__ int part[64];
    int t = threadIdx.x;
    for (int i = t; i < NN; i += 256) bsh[i] = __float_as_int(g_vfin[i]);
    if (t < 64) part[t] = 0;
    __syncthreads();
    int jl = t & 63;
    int j = blockIdx.x * 64 + jl;
    int stripe = t >> 6;
    if (j < NN) {
        int bj = bsh[j];
        int c = 0;
        int i0 = stripe * 2500, i1 = i0 + 2500;
        for (int i = i0; i < i1; ++i) {
            int bi = bsh[i];
            c += (bi < bj) || (bi == bj && i < j);
        }
        atomicAdd(&part[jl], c);
    }
    __syncthreads();
    if (t < 64) {
        int jj = blockIdx.x * 64 + t;
        if (jj < NN) g_rank[jj] = part[t];
    }
}

__device__ __forceinline__ unsigned ekey_hash(int key) {
    return ((unsigned)key * 2654435761u) >> 17;   // 15 bits
}

// ---- K6a: hash-insert undirected edge keys, track min edge index per key ----
__global__ void k_hashins(const int* __restrict__ edge) {
    int e = blockIdx.x * blockDim.x + threadIdx.x;
    if (e >= EE) return;
    int r = edge[e], c = edge[EE + e];
    int lo = min(r, c), hi = max(r, c);
    int key = lo * NN + hi;
    unsigned slot = ekey_hash(key) & HMASK;
    while (true) {
        int old = atomicCAS(&g_htkey[slot], -1, key);
        if (old == -1 || old == key) { atomicMin(&g_htmin[slot], e); break; }
        slot = (slot + 1) & HMASK;
    }
}

// ---- K6b: compact unique edges, gather ranks ----
__global__ void k_compact(const int* __restrict__ edge) {
    int e = blockIdx.x * blockDim.x + threadIdx.x;
    if (e >= EE) return;
    int r = edge[e], c = edge[EE + e];
    int lo = min(r, c), hi = max(r, c);
    int key = lo * NN + hi;
    unsigned slot = ekey_hash(key) & HMASK;
    while (g_htkey[slot] != key) slot = (slot + 1) & HMASK;
    if (g_htmin[slot] == e) {
        int j = atomicAdd(&g_ue_cnt, 1);
        g_ue_a[j] = g_rank[lo];
        g_ue_b[j] = g_rank[hi];
    }
}

// ---- K7: out[d] += sum_e X[a_e][d]*X[b_e][d].
//      SINGLE launch, grid (edge-blocks x D-tiles), x-fastest so each
//      D-tile's 40MB row-chunk working set stays L2-resident across its
//      250-CTA wave. Explicit 4-edge batching -> 8 indep loads in flight. ----
__global__ void __launch_bounds__(256) k_main(const float* __restrict__ X,
                                              float* __restrict__ out) {
    __shared__ int sa[EPB], sb[EPB];
    int nE = g_ue_cnt;
    int e0 = blockIdx.x * EPB;
    int t = threadIdx.x;
    int cnt = nE - e0;
    if (cnt > EPB) cnt = EPB;
    if (cnt > 0 && t < cnt) { sa[t] = g_ue_a[e0 + t]; sb[t] = g_ue_b[e0 + t]; }
    __syncthreads();
    if (cnt <= 0) return;
    int d = blockIdx.y * DCHUNK + t * 4;
    if (d >= DD) return;
    const float* Xd = X + d;
    float ax = 0.f, ay = 0.f, az = 0.f, aw = 0.f;
    int i = 0;
    for (; i + 4 <= cnt; i += 4) {
        float4 a0 = *(const float4*)(Xd + (size_t)sa[i]     * DD);
        float4 b0 = *(const float4*)(Xd + (size_t)sb[i]     * DD);
        float4 a1 = *(const float4*)(Xd + (size_t)sa[i + 1] * DD);
        float4 b1 = *(const float4*)(Xd + (size_t)sb[i + 1] * DD);
        float4 a2 = *(const float4*)(Xd + (size_t)sa[i + 2] * DD);
        float4 b2 = *(const float4*)(Xd + (size_t)sb[i + 2] * DD);
        float4 a3 = *(const float4*)(Xd + (size_t)sa[i + 3] * DD);
        float4 b3 = *(const float4*)(Xd + (size_t)sb[i + 3] * DD);
        ax += a0.x * b0.x; ay += a0.y * b0.y; az += a0.z * b0.z; aw += a0.w * b0.w;
        ax += a1.x * b1.x; ay += a1.y * b1.y; az += a1.z * b1.z; aw += a1.w * b1.w;
        ax += a2.x * b2.x; ay += a2.y * b2.y; az += a2.z * b2.z; aw += a2.w * b2.w;
        ax += a3.x * b3.x; ay += a3.y * b3.y; az += a3.z * b3.z; aw += a3.w * b3.w;
    }
    for (; i < cnt; ++i) {
        float4 a = *(const float4*)(Xd + (size_t)sa[i] * DD);
        float4 b = *(const float4*)(Xd + (size_t)sb[i] * DD);
        ax += a.x * b.x; ay += a.y * b.y; az += a.z * b.z; aw += a.w * b.w;
    }
    atomicAdd(&out[d + 0], ax);
    atomicAdd(&out[d + 1], ay);
    atomicAdd(&out[d + 2], az);
    atomicAdd(&out[d + 3], aw);
}

extern "C" void kernel_launch(void* const* d_in, const int* in_sizes, int n_in,
                              void* d_out, int out_size) {
    const int*   edge;
    const float* X;
    if (in_sizes[0] == 2 * EE) {
        edge = (const int*)d_in[0];
        X    = (const float*)d_in[1];
    } else {
        edge = (const int*)d_in[1];
        X    = (const float*)d_in[0];
    }
    float* out = (float*)d_out;   // [D]

    // match Python-float -> f32 casts of the reference exactly
    float Pf  = (float)((1.0 - 0.85) / 10000.0);
    float V0f = (float)(1.0 / 10000.0);

    // 208000B dynamic smem for pagerank (non-stream call; capture-safe)
    const int PR_SMEM = 2 * NN * 4 + EE * 4 + EE * 4;
    cudaFuncSetAttribute(k_pagerank, cudaFuncAttributeMaxDynamicSharedMemorySize, PR_SMEM);

    k_init<<<128, 256>>>(out);
    k_count<<<63, 256>>>(edge);
    k_vals<<<63, 256>>>(edge);
    k_scan<<<1, 1024>>>();
    k_chunkhist<<<NCHUNK, 512>>>(edge);
    k_place<<<63, 256>>>(edge);
    k_pagerank<<<1, 1024, PR_SMEM>>>(Pf, V0f);
    k_rank<<<157, 256>>>();
    k_hashins<<<63, 256>>>(edge);
    k_compact<<<63, 256>>>(edge);
    k_main<<<dim3(250, 10), 256>>>(X, out);
}

// round 14
// speedup vs baseline: 6.2970x; 1.0509x over previous
#include <cuda_runtime.h>

// Problem constants
#define NN      10000   // nodes
#define DD      10000   // hypervector dim
#define EE      16000   // edges
#define HSZ     32768   // hash table slots
#define HMASK   32767
#define NCHUNK  32      // edge chunks for stable CSR build
#define CHSZ    500     // edges per chunk (32*500 = 16000)
#define DCHUNK  1024    // D-dim tile (40MB working set -> L2 resident)
#define EPB     64      // edges per CTA in main kernel

// ---- scratch (device globals; no allocations allowed) ----
__device__ int   g_colcnt[NN];
__device__ int   g_rowcnt[NN];
__device__ int   g_rowoff[NN + 1];
__device__ float g_vals[EE];
__device__ int   g_wchunk[EE];
__device__ int   g_ghist[NCHUNK * NN];
__device__ int   g_csr_col[EE];
__device__ float g_csr_val[EE];
__device__ float g_vfin[NN];
__device__ int   g_rank[NN];
__device__ int   g_htkey[HSZ];
__device__ int   g_htmin[HSZ];
__device__ int   g_ucnt[NN];      // unique edges per lo
__device__ int   g_ucur[NN];      // placement cursor per lo
__device__ int   g_ueoff[NN + 1]; // scan of g_ucnt
__device__ int   g_ue_a[EE];
__device__ int   g_ue_b[EE];
__device__ int   g_ue_cnt;

// ---- K0: zero/seed scratch + output ----
__global__ void k_init(float* __restrict__ out) {
    int i = blockIdx.x * blockDim.x + threadIdx.x;   // 32768 threads
    if (i < DD) out[i] = 0.f;
    if (i < NN) { g_colcnt[i] = 0; g_rowcnt[i] = 0; g_ucnt[i] = 0; g_ucur[i] = 0; }
    if (i < HSZ) { g_htkey[i] = -1; g_htmin[i] = 0x7fffffff; }
}

// ---- K1: in-degree counts (col) and row counts ----
__global__ void k_count(const int* __restrict__ edge) {
    int e = blockIdx.x * blockDim.x + threadIdx.x;
    if (e < EE) {
        atomicAdd(&g_colcnt[edge[EE + e]], 1);   // col
        atomicAdd(&g_rowcnt[edge[e]], 1);        // row
    }
}

// ---- K2: vals[e] = 0.85f / count(col[e]) (IEEE rn division) ----
__global__ void k_vals(const int* __restrict__ edge) {
    int e = blockIdx.x * blockDim.x + threadIdx.x;
    if (e < EE)
        g_vals[e] = __fdiv_rn(0.85f, (float)g_colcnt[edge[EE + e]]);
}

// ---- K_scan2: warp-shuffle exclusive scan over NN counts.
//      which=0: g_rowcnt -> g_rowoff (+ total in g_rowoff[NN])
//      which=1: g_ucnt   -> g_ueoff  (+ total in g_ue_cnt) ----
__global__ void k_scan2(int which) {
    __shared__ int warpsum[32];
    int t = threadIdx.x;               // 1024 threads
    const int* cnt = which ? g_ucnt : g_rowcnt;
    int* off       = which ? g_ueoff : g_rowoff;
    int loc[10];
    int s = 0;
    if (t < 1000) {
        int base = t * 10;
        #pragma unroll
        for (int k = 0; k < 10; ++k) { loc[k] = s; s += cnt[base + k]; }
    }
    int lane = t & 31, wid = t >> 5;
    int v = s;
    #pragma unroll
    for (int o = 1; o < 32; o <<= 1) {
        int u = __shfl_up_sync(0xffffffffu, v, o);
        if (lane >= o) v += u;
    }
    if (lane == 31) warpsum[wid] = v;
    __syncthreads();
    if (wid == 0) {
        int w = warpsum[lane];
        #pragma unroll
        for (int o = 1; o < 32; o <<= 1) {
            int u = __shfl_up_sync(0xffffffffu, w, o);
            if (lane >= o) w += u;
        }
        warpsum[lane] = w;
    }
    __syncthreads();
    int incl = v + (wid ? warpsum[wid - 1] : 0);
    int excl = incl - s;
    if (t < 1000) {
        int base = t * 10;
        #pragma unroll
        for (int k = 0; k < 10; ++k) off[base + k] = excl + loc[k];
    }
    if (t == 1023) {
        if (which) g_ue_cnt = incl;
        else       g_rowoff[NN] = incl;
    }
}

// ---- K3b: per-chunk row histograms + within-chunk stable prefix counts ----
__global__ void k_chunkhist(const int* __restrict__ edge) {
    __shared__ int shist[NN];   // 40KB
    __shared__ int srow[CHSZ];
    int c = blockIdx.x, t = threadIdx.x;          // 32 CTAs x 512 threads
    for (int i = t; i < NN; i += 512) shist[i] = 0;
    if (t < CHSZ) srow[t] = edge[c * CHSZ + t];
    __syncthreads();
    if (t < CHSZ) {
        int r = srow[t];
        int w = 0;
        for (int j = 0; j < t; ++j) w += (srow[j] == r);
        g_wchunk[c * CHSZ + t] = w;
        atomicAdd(&shist[r], 1);
    }
    __syncthreads();
    for (int i = t; i < NN; i += 512) g_ghist[c * NN + i] = shist[i];
}

// ---- K3c: stable scatter into CSR (by row, edge-index order preserved) ----
__global__ void k_place(const int* __restrict__ edge) {
    int e = blockIdx.x * blockDim.x + threadIdx.x;
    if (e >= EE) return;
    int r = edge[e];
    int c = e / CHSZ;
    int w = g_wchunk[e];
    for (int c2 = 0; c2 < c; ++c2) w += g_ghist[c2 * NN + r];
    int pos = g_rowoff[r] + w;
    g_csr_col[pos] = edge[EE + e];
    g_csr_val[pos] = g_vals[e];
}

// ---- K4: PageRank, 10 iterations, single CTA, ALL data in dynamic shared.
//      P-BASE accumulation: acc = p; then += rn(val*v) in ascending edge
//      order, rn ops (no FMA). Certified semantics from R8. ----
__global__ void k_pagerank(float Pf, float V0f) {
    extern __shared__ unsigned char dynraw[];
    float* vsh  = (float*)dynraw;            // NN
    float* vnew = vsh + NN;                  // NN
    int*   scol = (int*)(vnew + NN);         // EE
    float* sval = (float*)(scol + EE);       // EE
    int t = threadIdx.x;
    for (int e = t; e < EE; e += 1024) { scol[e] = g_csr_col[e]; sval[e] = g_csr_val[e]; }
    for (int i = t; i < NN; i += 1024) vsh[i] = V0f;
    __syncthreads();
    for (int it = 0; it < 10; ++it) {
        for (int i = t; i < NN; i += 1024) {
            int s = g_rowoff[i], en = g_rowoff[i + 1];
            float acc = Pf;                                   // seed with p FIRST
            for (int k = s; k < en; ++k)
                acc = __fadd_rn(acc, __fmul_rn(sval[k], vsh[scol[k]]));
            vnew[i] = acc;
        }
        __syncthreads();
        for (int i = t; i < NN; i += 1024) vsh[i] = vnew[i];
        __syncthreads();
    }
    for (int i = t; i < NN; i += 1024) g_vfin[i] = vsh[i];
}

// ---- K5: stable-argsort ranks, striped (157 CTAs x 64 j's x 4 i-stripes).
//      rank(j) = #{i: v_i<v_j || (v_i==v_j && i<j)}. All v>0 -> int-bit cmp. ----
__global__ void __launch_bounds__(256) k_rank() {
    __shared__ int bsh[NN];   // 40KB
    __shared__ int part[64];
    int t = threadIdx.x;
    for (int i = t; i < NN; i += 256) bsh[i] = __float_as_int(g_vfin[i]);
    if (t < 64) part[t] = 0;
    __syncthreads();
    int jl = t & 63;
    int j = blockIdx.x * 64 + jl;
    int stripe = t >> 6;
    if (j < NN) {
        int bj = bsh[j];
        int c = 0;
        int i0 = stripe * 2500, i1 = i0 + 2500;
        for (int i = i0; i < i1; ++i) {
            int bi = bsh[i];
            c += (bi < bj) || (bi == bj && i < j);
        }
        atomicAdd(&part[jl], c);
    }
    __syncthreads();
    if (t < 64) {
        int jj = blockIdx.x * 64 + t;
        if (jj < NN) g_rank[jj] = part[t];
    }
}

__device__ __forceinline__ unsigned ekey_hash(int key) {
    return ((unsigned)key * 2654435761u) >> 17;   // 15 bits
}

// ---- K6a: hash-insert undirected edge keys, track min edge index per key ----
__global__ void k_hashins(const int* __restrict__ edge) {
    int e = blockIdx.x * blockDim.x + threadIdx.x;
    if (e >= EE) return;
    int r = edge[e], c = edge[EE + e];
    int lo = min(r, c), hi = max(r, c);
    int key = lo * NN + hi;
    unsigned slot = ekey_hash(key) & HMASK;
    while (true) {
        int old = atomicCAS(&g_htkey[slot], -1, key);
        if (old == -1 || old == key) { atomicMin(&g_htmin[slot], e); break; }
        slot = (slot + 1) & HMASK;
    }
}

// ---- K6b: count unique edges per lo node ----
__global__ void k_ucount(const int* __restrict__ edge) {
    int e = blockIdx.x * blockDim.x + threadIdx.x;
    if (e >= EE) return;
    int r = edge[e], c = edge[EE + e];
    int lo = min(r, c), hi = max(r, c);
    int key = lo * NN + hi;
    unsigned slot = ekey_hash(key) & HMASK;
    while (g_htkey[slot] != key) slot = (slot + 1) & HMASK;
    if (g_htmin[slot] == e) atomicAdd(&g_ucnt[lo], 1);
}

// ---- K6c: place unique edges grouped by lo (order within group arbitrary).
//      Grouping puts duplicate a-rows adjacent in k_main -> L1/MSHR hits. ----
__global__ void k_uplace(const int* __restrict__ edge) {
    int e = blockIdx.x * blockDim.x + threadIdx.x;
    if (e >= EE) return;
    int r = edge[e], c = edge[EE + e];
    int lo = min(r, c), hi = max(r, c);
    int key = lo * NN + hi;
    unsigned slot = ekey_hash(key) & HMASK;
    while (g_htkey[slot] != key) slot = (slot + 1) & HMASK;
    if (g_htmin[slot] == e) {
        int pos = g_ueoff[lo] + atomicAdd(&g_ucur[lo], 1);
        g_ue_a[pos] = g_rank[lo];
        g_ue_b[pos] = g_rank[hi];
    }
}

// ---- K7: out[d] += sum_e X[a_e][d]*X[b_e][d].
//      SINGLE launch, grid (edge-blocks x D-tiles), x-fastest so each
//      D-tile's 40MB row-chunk working set stays L2-resident across its
//      250-CTA wave. Explicit 4-edge batching -> 8 indep loads in flight.
//      Edges arrive lo-grouped so duplicate a-rows hit L1. ----
__global__ void __launch_bounds__(256) k_main(const float* __restrict__ X,
                                              float* __restrict__ out) {
    __shared__ int sa[EPB], sb[EPB];
    int nE = g_ue_cnt;
    int e0 = blockIdx.x * EPB;
    int t = threadIdx.x;
    int cnt = nE - e0;
    if (cnt > EPB) cnt = EPB;
    if (cnt > 0 && t < cnt) { sa[t] = g_ue_a[e0 + t]; sb[t] = g_ue_b[e0 + t]; }
    __syncthreads();
    if (cnt <= 0) return;
    int d = blockIdx.y * DCHUNK + t * 4;
    if (d >= DD) return;
    const float* Xd = X + d;
    float ax = 0.f, ay = 0.f, az = 0.f, aw = 0.f;
    int i = 0;
    for (; i + 4 <= cnt; i += 4) {
        float4 a0 = *(const float4*)(Xd + (size_t)sa[i]     * DD);
        float4 b0 = *(const float4*)(Xd + (size_t)sb[i]     * DD);
        float4 a1 = *(const float4*)(Xd + (size_t)sa[i + 1] * DD);
        float4 b1 = *(const float4*)(Xd + (size_t)sb[i + 1] * DD);
        float4 a2 = *(const float4*)(Xd + (size_t)sa[i + 2] * DD);
        float4 b2 = *(const float4*)(Xd + (size_t)sb[i + 2] * DD);
        float4 a3 = *(const float4*)(Xd + (size_t)sa[i + 3] * DD);
        float4 b3 = *(const float4*)(Xd + (size_t)sb[i + 3] * DD);
        ax += a0.x * b0.x; ay += a0.y * b0.y; az += a0.z * b0.z; aw += a0.w * b0.w;
        ax += a1.x * b1.x; ay += a1.y * b1.y; az += a1.z * b1.z; aw += a1.w * b1.w;
        ax += a2.x * b2.x; ay += a2.y * b2.y; az += a2.z * b2.z; aw += a2.w * b2.w;
        ax += a3.x * b3.x; ay += a3.y * b3.y; az += a3.z * b3.z; aw += a3.w * b3.w;
    }
    for (; i < cnt; ++i) {
        float4 a = *(const float4*)(Xd + (size_t)sa[i] * DD);
        float4 b = *(const float4*)(Xd + (size_t)sb[i] * DD);
        ax += a.x * b.x; ay += a.y * b.y; az += a.z * b.z; aw += a.w * b.w;
    }
    atomicAdd(&out[d + 0], ax);
    atomicAdd(&out[d + 1], ay);
    atomicAdd(&out[d + 2], az);
    atomicAdd(&out[d + 3], aw);
}

extern "C" void kernel_launch(void* const* d_in, const int* in_sizes, int n_in,
                              void* d_out, int out_size) {
    const int*   edge;
    const float* X;
    if (in_sizes[0] == 2 * EE) {
        edge = (const int*)d_in[0];
        X    = (const float*)d_in[1];
    } else {
        edge = (const int*)d_in[1];
        X    = (const float*)d_in[0];
    }
    float* out = (float*)d_out;   // [D]

    // match Python-float -> f32 casts of the reference exactly
    float Pf  = (float)((1.0 - 0.85) / 10000.0);
    float V0f = (float)(1.0 / 10000.0);

    // 208000B dynamic smem for pagerank (non-stream call; capture-safe)
    const int PR_SMEM = 2 * NN * 4 + EE * 4 + EE * 4;
    cudaFuncSetAttribute(k_pagerank, cudaFuncAttributeMaxDynamicSharedMemorySize, PR_SMEM);

    k_init<<<128, 256>>>(out);
    k_count<<<63, 256>>>(edge);
    k_vals<<<63, 256>>>(edge);
    k_scan2<<<1, 1024>>>(0);
    k_chunkhist<<<NCHUNK, 512>>>(edge);
    k_place<<<63, 256>>>(edge);
    k_pagerank<<<1, 1024, PR_SMEM>>>(Pf, V0f);
    k_rank<<<157, 256>>>();
    k_hashins<<<63, 256>>>(edge);
    k_ucount<<<63, 256>>>(edge);
    k_scan2<<<1, 1024>>>(1);
    k_uplace<<<63, 256>>>(edge);
    k_main<<<dim3(250, 10), 256>>>(X, out);
}